// round 1
// baseline (speedup 1.0000x reference)
#include <cuda_runtime.h>
#include <cuda_bf16.h>
#include <cstdint>

// Problem constants (fixed shapes from reference)
#define BB 16
#define LL 2048
#define DD 64
#define BQ 16          // q rows per CTA
#define TK 64          // k cols per tile
#define NT (LL / TK)   // 32 k tiles
#define PITCH 2049     // scores row pitch (floats) -> bank-conflict-free row writes
#define NTHREADS 512

// smem layout (floats):
//   scores: BQ * PITCH            = 32784
//   qs:     BQ * 68               = 1088
//   ks:     2  * TK * DD          = 8192
#define SC_WORDS (BQ * PITCH)
#define QS_WORDS (BQ * 68)
#define KS_WORDS (2 * TK * DD)
#define SMEM_WORDS (SC_WORDS + QS_WORDS + KS_WORDS)
#define SMEM_BYTES (SMEM_WORDS * 4)

__device__ __forceinline__ void fma2(unsigned long long& acc,
                                     unsigned long long a,
                                     unsigned long long b) {
    asm volatile("fma.rn.f32x2 %0, %1, %2, %0;" : "+l"(acc) : "l"(a), "l"(b));
}

__device__ __forceinline__ float hsum2(unsigned long long a) {
    float lo, hi;
    asm("mov.b64 {%0, %1}, %2;" : "=f"(lo), "=f"(hi) : "l"(a));
    return lo + hi;
}

__device__ __forceinline__ void cp16(uint32_t dst_smem, const float* src) {
    asm volatile("cp.async.cg.shared.global [%0], [%1], 16;\n"
                 :: "r"(dst_smem), "l"(src));
}
__device__ __forceinline__ void cp_commit() {
    asm volatile("cp.async.commit_group;\n");
}
template <int N>
__device__ __forceinline__ void cp_wait() {
    asm volatile("cp.async.wait_group %0;\n" :: "n"(N));
}

__global__ void __launch_bounds__(NTHREADS, 1)
attn_kernel(const float* __restrict__ q,
            const float* __restrict__ k,
            float* __restrict__ out_attn) {
    extern __shared__ float smem[];
    float* sc = smem;                       // [BQ][PITCH]
    float* qs = smem + SC_WORDS;            // [BQ][68]
    float* ks = qs + QS_WORDS;              // [2][TK][DD]

    const int b  = blockIdx.y;
    const int qt = blockIdx.x;

    const float* qp = q + ((size_t)b * LL + (size_t)qt * BQ) * DD;
    const float* kp = k + (size_t)b * LL * DD;
    float* outp = out_attn + ((size_t)b * LL + (size_t)qt * BQ) * (size_t)LL;

    const int tid = threadIdx.x;
    const int w   = tid >> 5;
    const int l   = tid & 31;
    const int qrow = l & 15;
    const int cg   = w + ((l >> 4) << 4);   // 0..31, banks split across half-warps

    const uint32_t ks_base = (uint32_t)__cvta_generic_to_shared(ks);

    // ---- stage q tile into smem (coalesced), then into registers ----
    for (int i = tid; i < BQ * DD; i += NTHREADS) {
        int r = i >> 6, d = i & 63;
        qs[r * 68 + d] = qp[r * DD + d];
    }

    // ---- prefetch k tile 0 via cp.async ----
    {
        int chunk = tid;                    // 16B chunks; 1024 per tile
        #pragma unroll
        for (int rep = 0; rep < 2; rep++) {
            int row = chunk >> 4, d4 = chunk & 15;
            cp16(ks_base + (uint32_t)chunk * 16u,
                 kp + ((size_t)row * DD + (size_t)d4 * 4));
            chunk += NTHREADS;
        }
        cp_commit();
    }

    __syncthreads();

    // q row -> registers as f32x2 pairs
    ulonglong2 qv[16];
    #pragma unroll
    for (int i = 0; i < 16; i++)
        qv[i] = *(const ulonglong2*)&qs[qrow * 68 + i * 4];

    const int c0 = cg;
    const int c1 = cg + 32;

    // ---- mainloop over k tiles ----
    for (int kt = 0; kt < NT; kt++) {
        // prefetch next tile
        if (kt + 1 < NT) {
            const float* kn = kp + (size_t)(kt + 1) * TK * DD;
            uint32_t dbuf = ks_base + (uint32_t)(((kt + 1) & 1) * TK * DD) * 4u;
            int chunk = tid;
            #pragma unroll
            for (int rep = 0; rep < 2; rep++) {
                int row = chunk >> 4, d4 = chunk & 15;
                cp16(dbuf + (uint32_t)chunk * 16u,
                     kn + ((size_t)row * DD + (size_t)d4 * 4));
                chunk += NTHREADS;
            }
            cp_commit();
            cp_wait<1>();
        } else {
            cp_wait<0>();
        }
        __syncthreads();

        const float* kb = ks + (kt & 1) * (TK * DD);

        unsigned long long a0 = 0ull, a1 = 0ull, b0 = 0ull, b1 = 0ull;
        #pragma unroll
        for (int i = 0; i < 16; i++) {
            ulonglong2 k0 = *(const ulonglong2*)&kb[c0 * DD + i * 4];
            ulonglong2 k1 = *(const ulonglong2*)&kb[c1 * DD + i * 4];
            fma2(a0, qv[i].x, k0.x);
            fma2(a1, qv[i].y, k0.y);
            fma2(b0, qv[i].x, k1.x);
            fma2(b1, qv[i].y, k1.y);
        }
        float s0 = hsum2(a0) + hsum2(a1);
        float s1 = hsum2(b0) + hsum2(b1);

        sc[qrow * PITCH + kt * TK + c0] = s0;
        sc[qrow * PITCH + kt * TK + c1] = s1;

        __syncthreads();
    }

    // ---- softmax: warp w owns row w ----
    {
        float* row = sc + w * PITCH;
        float mx = -1e30f;
        #pragma unroll 8
        for (int i = l; i < LL; i += 32)
            mx = fmaxf(mx, row[i]);
        #pragma unroll
        for (int o = 16; o > 0; o >>= 1)
            mx = fmaxf(mx, __shfl_xor_sync(0xFFFFFFFFu, mx, o));

        float sum = 0.0f;
        #pragma unroll 8
        for (int i = l; i < LL; i += 32) {
            float e = __expf(row[i] - mx);
            row[i] = e;
            sum += e;
        }
        #pragma unroll
        for (int o = 16; o > 0; o >>= 1)
            sum += __shfl_xor_sync(0xFFFFFFFFu, sum, o);

        float inv = 1.0f / sum;
        float* orow = outp + (size_t)w * LL;
        #pragma unroll 8
        for (int i = l; i < LL; i += 32)
            orow[i] = row[i] * inv;
    }
}

extern "C" void kernel_launch(void* const* d_in, const int* in_sizes, int n_in,
                              void* d_out, int out_size) {
    const float* q = (const float*)d_in[0];
    const float* k = (const float*)d_in[1];
    const float* v = (const float*)d_in[2];
    float* out = (float*)d_out;

    // output layout: [v : B*L*D floats][attention : B*L*L floats]
    const size_t v_elems = (size_t)BB * LL * DD;

    cudaMemcpyAsync(out, v, v_elems * sizeof(float), cudaMemcpyDeviceToDevice);

    cudaFuncSetAttribute(attn_kernel,
                         cudaFuncAttributeMaxDynamicSharedMemorySize,
                         SMEM_BYTES);

    dim3 grid(LL / BQ, BB);   // (128, 16) = 2048 CTAs
    dim3 block(NTHREADS);
    attn_kernel<<<grid, block, SMEM_BYTES>>>(q, k, out + v_elems);
}